// round 6
// baseline (speedup 1.0000x reference)
#include <cuda_runtime.h>
#include <cstdint>
#include <cstddef>

#define TGT 256
#define BSZ 8
#define EDIM 256
#define SRCL 4096
#define PARTSZ (BSZ * TGT * EDIM)
#define SPLITK 4

// Split-K partials for GEMM1 (4 x 2MB)
__device__ float g_O[SPLITK * PARTSZ];

// swizzles: SW128 for 128B rows, SW64 for 64B rows
#define SWZ(o)   ((o) ^ (((o) >> 3) & 0x70u))
#define SWZ64(o) ((o) ^ (((o) >> 3) & 0x30u))

// per-buffer smem (bytes): A_hi 0, A_lo 4096, B_hi 8192, B_lo 12288
#define SM_AH 0
#define SM_AL 4096
#define SM_BH 8192
#define SM_BL 12288
#define BUF_BYTES 16384
#define SMEM_BYTES (2 * BUF_BYTES)

static __device__ __forceinline__ uint32_t smem_u32(const void* p) {
    uint32_t a;
    asm("{ .reg .u64 t; cvta.to.shared.u64 t, %1; cvt.u32.u64 %0, t; }" : "=r"(a) : "l"(p));
    return a;
}
// fp32 pair -> bf16x2 hi + bf16x2 lo (2-term split)
static __device__ __forceinline__ void cvt2(float x0, float x1, uint32_t& h, uint32_t& l) {
    asm("cvt.rn.bf16x2.f32 %0, %1, %2;" : "=r"(h) : "f"(x1), "f"(x0));
    float h0 = __uint_as_float(h << 16);
    float h1 = __uint_as_float(h & 0xffff0000u);
    float r0 = x0 - h0;
    float r1 = x1 - h1;
    asm("cvt.rn.bf16x2.f32 %0, %1, %2;" : "=r"(l) : "f"(r1), "f"(r0));
}
static __device__ __forceinline__ void sts64(uint32_t addr, uint32_t a, uint32_t b) {
    asm volatile("st.shared.v2.b32 [%0], {%1, %2};" :: "r"(addr), "r"(a), "r"(b) : "memory");
}
static __device__ __forceinline__ void ldsm_x4(uint32_t& r0, uint32_t& r1, uint32_t& r2,
                                               uint32_t& r3, uint32_t addr) {
    asm volatile("ldmatrix.sync.aligned.m8n8.x4.shared.b16 {%0,%1,%2,%3}, [%4];"
                 : "=r"(r0), "=r"(r1), "=r"(r2), "=r"(r3) : "r"(addr));
}
static __device__ __forceinline__ void ldsm_x2(uint32_t& r0, uint32_t& r1, uint32_t addr) {
    asm volatile("ldmatrix.sync.aligned.m8n8.x2.shared.b16 {%0,%1}, [%2];"
                 : "=r"(r0), "=r"(r1) : "r"(addr));
}
static __device__ __forceinline__ void ldsm_x2t(uint32_t& r0, uint32_t& r1, uint32_t addr) {
    asm volatile("ldmatrix.sync.aligned.m8n8.x2.trans.shared.b16 {%0,%1}, [%2];"
                 : "=r"(r0), "=r"(r1) : "r"(addr));
}
static __device__ __forceinline__ void mma_bf16(float& c0, float& c1, float& c2, float& c3,
                                                uint32_t a0, uint32_t a1, uint32_t a2,
                                                uint32_t a3, uint32_t b0, uint32_t b1) {
    asm volatile(
        "mma.sync.aligned.m16n8k16.row.col.f32.bf16.bf16.f32 "
        "{%0,%1,%2,%3}, {%4,%5,%6,%7}, {%8,%9}, {%0,%1,%2,%3};"
        : "+f"(c0), "+f"(c1), "+f"(c2), "+f"(c3)
        : "r"(a0), "r"(a1), "r"(a2), "r"(a3), "r"(b0), "r"(b1));
}

// CTA tile 64x64, 128 threads (4 warps as 2M x 2N, warp tile 32x32), BK=32.
// MODE 0: partial X_b[64x64] over K/4 = mask_b @ value_b  (+ fused weights copy)
//         blockIdx.z = b*4 + ks. B gathered [k][n] (trans ldmatrix, SW128 rows).
// MODE 1: out[64x64] = (sum of 4 partials)[64x256] @ W^T + bias. B = W rows [n][k] (SW64).
template <int MODE>
__global__ void __launch_bounds__(128, 4) mma_gemm(
    const float* __restrict__ Asrc, const float* __restrict__ Bsrc,
    const float* __restrict__ bias, float* __restrict__ outp,
    float* __restrict__ weights)
{
    extern __shared__ char smem[];
    const uint32_t sb = smem_u32(smem);
    const int tid  = threadIdx.x;
    const int wid  = tid >> 5;
    const int lane = tid & 31;
    const int b    = (MODE == 0) ? (blockIdx.z >> 2) : blockIdx.z;
    const int ks   = (MODE == 0) ? (blockIdx.z & 3) : 0;
    const int m0   = blockIdx.y * 64;
    const int n0   = blockIdx.x * 64;
    const int wm   = wid & 1;        // 2 warps in M (32 rows each)
    const int wn   = wid >> 1;       // 2 warps in N (32 cols each)
    constexpr int K   = (MODE == 0) ? SRCL : EDIM;           // A row stride
    constexpr int KC  = (MODE == 0) ? (SRCL / SPLITK) : EDIM; // K per CTA
    constexpr int NC  = KC / 32;
    const int kbase = ks * KC;

    const float* Ag = ((MODE == 0) ? Asrc : (const float*)g_O) + ((size_t)b * TGT + m0) * K;

    float acc[2][4][4];
#pragma unroll
    for (int i = 0; i < 2; i++)
#pragma unroll
        for (int j = 0; j < 4; j++)
#pragma unroll
            for (int q = 0; q < 4; q++) acc[i][j][q] = 0.f;

    float4 aR[4], bR[4];

    const int rA  = tid >> 3;       // 0..15 (A/B-mode1 row sub-index)
    const int cA  = tid & 7;        // 0..7  float4 col (of 8)
    const int rB0 = tid >> 4;       // 0..7  (B mode0 k-row sub-index)
    const int cB0 = tid & 15;       // 0..15 float4 col (of 16)

    auto load_chunk = [&](int k0) {
        const bool docopy = (MODE == 0) && ((k0 >> 8) == (int)blockIdx.x);
#pragma unroll
        for (int j = 0; j < 4; ++j) {
            if (MODE == 0) {
                int arow = j * 16 + rA;
                aR[j] = *(const float4*)(Ag + (size_t)arow * K + kbase + k0 + cA * 4);
                if (docopy)
                    *(float4*)(weights + ((size_t)b * TGT + m0 + arow) * SRCL + kbase + k0 + cA * 4) = aR[j];
                int krow = j * 8 + rB0;
                bR[j] = *(const float4*)(Bsrc + (size_t)(kbase + k0 + krow) * (BSZ * EDIM) + b * EDIM + n0 + cB0 * 4);
            } else {
                int arow = j * 16 + rA;
                const float* a0 = Ag + (size_t)arow * K + k0 + cA * 4;
                float4 v = *(const float4*)a0;
                float4 v1 = *(const float4*)(a0 + PARTSZ);
                float4 v2 = *(const float4*)(a0 + 2 * PARTSZ);
                float4 v3 = *(const float4*)(a0 + 3 * PARTSZ);
                v.x += v1.x + v2.x + v3.x;
                v.y += v1.y + v2.y + v3.y;
                v.z += v1.z + v2.z + v3.z;
                v.w += v1.w + v2.w + v3.w;
                aR[j] = v;
                int nrow = j * 16 + rA;
                bR[j] = *(const float4*)(Bsrc + (size_t)(n0 + nrow) * EDIM + k0 + cA * 4);
            }
        }
    };

    load_chunk(0);

#pragma unroll 1
    for (int c = 0; c < NC; ++c) {
        const uint32_t bufb = sb + (uint32_t)(c & 1) * BUF_BYTES;
        // ---- stage: convert + STS ----
#pragma unroll
        for (int j = 0; j < 4; ++j) {
            uint32_t h0, l0, h1, l1;
            // A: rows 64, 64B rows, SW64
            {
                int row = j * 16 + rA;
                uint32_t off = SWZ64((uint32_t)(row * 64 + cA * 8));
                cvt2(aR[j].x, aR[j].y, h0, l0);
                cvt2(aR[j].z, aR[j].w, h1, l1);
                // 8B sts: two bf16x2 = 4 bf16 = cols cA*4..+3
                uint32_t lo16 = (h0 & 0xffffu) | (h1 << 16);       // placeholder no
                (void)lo16;
                sts64(bufb + SM_AH + off, h0, h1);
                sts64(bufb + SM_AL + off, l0, l1);
            }
            if (MODE == 0) {
                int row = j * 8 + rB0;   // k-row, 128B rows, SW128
                uint32_t off = SWZ((uint32_t)(row * 128 + cB0 * 8));
                cvt2(bR[j].x, bR[j].y, h0, l0);
                cvt2(bR[j].z, bR[j].w, h1, l1);
                sts64(bufb + SM_BH + off, h0, h1);
                sts64(bufb + SM_BL + off, l0, l1);
            } else {
                int row = j * 16 + rA;   // n-row, 64B rows, SW64
                uint32_t off = SWZ64((uint32_t)(row * 64 + cA * 8));
                cvt2(bR[j].x, bR[j].y, h0, l0);
                cvt2(bR[j].z, bR[j].w, h1, l1);
                sts64(bufb + SM_BH + off, h0, h1);
                sts64(bufb + SM_BL + off, l0, l1);
            }
        }
        __syncthreads();   // single barrier per chunk (double buffered)

        // ---- prefetch next chunk ----
        if (c + 1 < NC) load_chunk((c + 1) * 32);

        // ---- MMA over staged chunk: 2 k16 steps ----
        const int r16 = lane & 15;
        const int hA  = lane >> 4;
#pragma unroll
        for (int kk = 0; kk < 2; ++kk) {
            uint32_t ah[2][4], al[2][4];
#pragma unroll
            for (int mi = 0; mi < 2; ++mi) {
                uint32_t off = SWZ64((uint32_t)((wm * 32 + mi * 16 + r16) * 64 + kk * 32 + hA * 16));
                ldsm_x4(ah[mi][0], ah[mi][1], ah[mi][2], ah[mi][3], bufb + SM_AH + off);
                ldsm_x4(al[mi][0], al[mi][1], al[mi][2], al[mi][3], bufb + SM_AL + off);
            }
            uint32_t bh[4][2], bl[4][2];
#pragma unroll
            for (int j = 0; j < 4; ++j) {
                if (MODE == 0) {
                    uint32_t off = SWZ((uint32_t)((kk * 16 + r16) * 128 + (wn * 32 + j * 8) * 2));
                    ldsm_x2t(bh[j][0], bh[j][1], bufb + SM_BH + off);
                    ldsm_x2t(bl[j][0], bl[j][1], bufb + SM_BL + off);
                } else {
                    int r8 = lane & 7, hb = (lane >> 3) & 1;
                    uint32_t off = SWZ64((uint32_t)((wn * 32 + j * 8 + r8) * 64 + kk * 32 + hb * 16));
                    ldsm_x2(bh[j][0], bh[j][1], bufb + SM_BH + off);
                    ldsm_x2(bl[j][0], bl[j][1], bufb + SM_BL + off);
                }
            }
#pragma unroll
            for (int mi = 0; mi < 2; ++mi)
#pragma unroll
                for (int j = 0; j < 4; ++j) {
                    mma_bf16(acc[mi][j][0], acc[mi][j][1], acc[mi][j][2], acc[mi][j][3],
                             ah[mi][0], ah[mi][1], ah[mi][2], ah[mi][3], bh[j][0], bh[j][1]);
                    mma_bf16(acc[mi][j][0], acc[mi][j][1], acc[mi][j][2], acc[mi][j][3],
                             ah[mi][0], ah[mi][1], ah[mi][2], ah[mi][3], bl[j][0], bl[j][1]);
                    mma_bf16(acc[mi][j][0], acc[mi][j][1], acc[mi][j][2], acc[mi][j][3],
                             al[mi][0], al[mi][1], al[mi][2], al[mi][3], bh[j][0], bh[j][1]);
                }
        }
    }

    // ---- epilogue ----
    const int quad = lane >> 2;
    const int qt   = lane & 3;
#pragma unroll
    for (int mi = 0; mi < 2; ++mi)
#pragma unroll
        for (int j = 0; j < 4; ++j) {
            int row = m0 + wm * 32 + mi * 16 + quad;
            int col = n0 + wn * 32 + j * 8 + qt * 2;
            if (MODE == 0) {
                float* o0 = g_O + (size_t)ks * PARTSZ + ((size_t)b * TGT + row) * EDIM + col;
                *(float2*)o0 = make_float2(acc[mi][j][0], acc[mi][j][1]);
                *(float2*)(o0 + 8 * EDIM) = make_float2(acc[mi][j][2], acc[mi][j][3]);
            } else {
                float2 bb = *(const float2*)(bias + col);
                *(float2*)(outp + ((size_t)row * BSZ + b) * EDIM + col) =
                    make_float2(acc[mi][j][0] + bb.x, acc[mi][j][1] + bb.y);
                *(float2*)(outp + ((size_t)(row + 8) * BSZ + b) * EDIM + col) =
                    make_float2(acc[mi][j][2] + bb.x, acc[mi][j][3] + bb.y);
            }
        }
}

extern "C" void kernel_launch(void* const* d_in, const int* in_sizes, int n_in,
                              void* d_out, int out_size) {
    const float* value = (const float*)d_in[2];
    const float* mask  = (const float*)d_in[3];
    const float* W     = (const float*)d_in[4];
    const float* bias  = (const float*)d_in[5];
    float* out = (float*)d_out;

    float* attn_out = out;                               // (TGT, BSZ, E)
    float* weights  = out + (size_t)TGT * BSZ * EDIM;    // (BSZ, TGT, SRC)

    cudaFuncSetAttribute(mma_gemm<0>, cudaFuncAttributeMaxDynamicSharedMemorySize, SMEM_BYTES);
    cudaFuncSetAttribute(mma_gemm<1>, cudaFuncAttributeMaxDynamicSharedMemorySize, SMEM_BYTES);

    // GEMM1: split-K=4; 512 CTAs. Fused weights copy.
    dim3 grid1(4, 4, BSZ * SPLITK);
    mma_gemm<0><<<grid1, 128, SMEM_BYTES>>>(mask, value, nullptr, nullptr, weights);
    // GEMM2: out = (sum partials) @ W^T + bias; 128 CTAs.
    dim3 grid2(4, 4, BSZ);
    mma_gemm<1><<<grid2, 128, SMEM_BYTES>>>(nullptr, W, bias, attn_out, nullptr);
}

// round 8
// speedup vs baseline: 1.3380x; 1.3380x over previous
#include <cuda_runtime.h>
#include <cuda_bf16.h>
#include <cstdint>
#include <cstddef>

#define TGT 256
#define BSZ 8
#define EDIM 256
#define SRCL 4096
#define PARTSZ (BSZ * TGT * EDIM)
#define SPLITK 4

// Split-K partials for GEMM1 (4 x 2MB)
__device__ float g_O[SPLITK * PARTSZ];
// Pre-converted value: [b][n][k] bf16 hi/lo (16.7MB each)
__device__ __nv_bfloat16 g_vhi[BSZ * EDIM * SRCL];
__device__ __nv_bfloat16 g_vlo[BSZ * EDIM * SRCL];

#define SWZ(o) ((o) ^ (((o) >> 3) & 0x70u))

static __device__ __forceinline__ uint32_t smem_u32(const void* p) {
    uint32_t a;
    asm("{ .reg .u64 t; cvta.to.shared.u64 t, %1; cvt.u32.u64 %0, t; }" : "=r"(a) : "l"(p));
    return a;
}
// fp32 pair -> bf16x2 hi + bf16x2 lo (x0 in low half)
static __device__ __forceinline__ void cvt2(float x0, float x1, uint32_t& h, uint32_t& l) {
    asm("cvt.rn.bf16x2.f32 %0, %1, %2;" : "=r"(h) : "f"(x1), "f"(x0));
    float h0 = __uint_as_float(h << 16);
    float h1 = __uint_as_float(h & 0xffff0000u);
    float r0 = x0 - h0;
    float r1 = x1 - h1;
    asm("cvt.rn.bf16x2.f32 %0, %1, %2;" : "=r"(l) : "f"(r1), "f"(r0));
}
static __device__ __forceinline__ void sts64(uint32_t addr, uint32_t a, uint32_t b) {
    asm volatile("st.shared.v2.b32 [%0], {%1, %2};" :: "r"(addr), "r"(a), "r"(b) : "memory");
}
static __device__ __forceinline__ void cpasync16(uint32_t dst, const void* src) {
    asm volatile("cp.async.cg.shared.global [%0], [%1], 16;" :: "r"(dst), "l"(src) : "memory");
}
static __device__ __forceinline__ void cpasync_commit() {
    asm volatile("cp.async.commit_group;" ::: "memory");
}
static __device__ __forceinline__ void cpasync_wait0() {
    asm volatile("cp.async.wait_group 0;" ::: "memory");
}
static __device__ __forceinline__ void ldsm_x4(uint32_t& r0, uint32_t& r1, uint32_t& r2,
                                               uint32_t& r3, uint32_t addr) {
    asm volatile("ldmatrix.sync.aligned.m8n8.x4.shared.b16 {%0,%1,%2,%3}, [%4];"
                 : "=r"(r0), "=r"(r1), "=r"(r2), "=r"(r3) : "r"(addr));
}
static __device__ __forceinline__ void ldsm_x2(uint32_t& r0, uint32_t& r1, uint32_t addr) {
    asm volatile("ldmatrix.sync.aligned.m8n8.x2.shared.b16 {%0,%1}, [%2];"
                 : "=r"(r0), "=r"(r1) : "r"(addr));
}
static __device__ __forceinline__ void mma_bf16(float& c0, float& c1, float& c2, float& c3,
                                                uint32_t a0, uint32_t a1, uint32_t a2,
                                                uint32_t a3, uint32_t b0, uint32_t b1) {
    asm volatile(
        "mma.sync.aligned.m16n8k16.row.col.f32.bf16.bf16.f32 "
        "{%0,%1,%2,%3}, {%4,%5,%6,%7}, {%8,%9}, {%0,%1,%2,%3};"
        : "+f"(c0), "+f"(c1), "+f"(c2), "+f"(c3)
        : "r"(a0), "r"(a1), "r"(a2), "r"(a3), "r"(b0), "r"(b1));
}

// ---------------------------------------------------------------------------
// prep: value fp32 [k][b][n] -> g_vhi/g_vlo bf16 [b][n][k] (K-major)
// tile 64k x 32n per block, block(32,8)
// ---------------------------------------------------------------------------
__global__ void __launch_bounds__(256) prep_value(const float* __restrict__ value) {
    __shared__ float s[64][33];
    const int k0 = blockIdx.x * 64;
    const int n0 = blockIdx.y * 32;
    const int b  = blockIdx.z;
    const int tx = threadIdx.x, ty = threadIdx.y;
#pragma unroll
    for (int i = 0; i < 8; ++i) {
        int k = ty + i * 8;
        s[k][tx] = value[(size_t)(k0 + k) * (BSZ * EDIM) + b * EDIM + n0 + tx];
    }
    __syncthreads();
    uint32_t* vhi32 = reinterpret_cast<uint32_t*>(g_vhi);
    uint32_t* vlo32 = reinterpret_cast<uint32_t*>(g_vlo);
#pragma unroll
    for (int i = 0; i < 4; ++i) {
        int n = ty + i * 8;
        float v0 = s[tx * 2][n];
        float v1 = s[tx * 2 + 1][n];
        uint32_t h, l;
        cvt2(v0, v1, h, l);
        size_t o = ((size_t)(b * EDIM + n0 + n) * SRCL + k0) / 2 + tx;
        vhi32[o] = h;
        vlo32[o] = l;
    }
}

// ---------------------------------------------------------------------------
// GEMM1: partial X_b[128x128] over K/4 = mask_b @ value_b  (+ fused weights copy)
// 256 thr, 8 warps as 2M x 4N (warp 64x32), BK=64, double buffered.
// A: fp32 LDG -> cvt2 -> STS. B: cp.async of prepped bf16 [n][k].
// grid (2 n, 2 m, 8b*4ks)
// ---------------------------------------------------------------------------
#define G1_STAGE 65536   // AH 16K | AL 16K | BH 16K | BL 16K
#define G1_SMEM (2 * G1_STAGE)

__global__ void __launch_bounds__(256, 1) gemm1_kernel(
    const float* __restrict__ mask, float* __restrict__ weights)
{
    extern __shared__ char smem[];
    const uint32_t sb = smem_u32(smem);
    const int tid  = threadIdx.x;
    const int wid  = tid >> 5;
    const int lane = tid & 31;
    const int bx   = blockIdx.x;            // n-tile
    const int m0   = blockIdx.y * 128;
    const int n0   = bx * 128;
    const int b    = blockIdx.z >> 2;
    const int ks   = blockIdx.z & 3;
    const int wm   = wid & 1;               // 2 M warps (64 rows)
    const int wn   = wid >> 1;              // 4 N warps (32 cols)
    const int kbase = ks * (SRCL / SPLITK); // KC = 1024
    constexpr int NC = (SRCL / SPLITK) / 64;  // 16 chunks

    const float* Ab = mask + ((size_t)b * TGT + m0) * SRCL;

    const int arow = tid >> 4;   // 0..15 (+p*16)
    const int ac4  = tid & 15;   // float4 col

    float acc[4][4][4];
#pragma unroll
    for (int i = 0; i < 4; i++)
#pragma unroll
        for (int j = 0; j < 4; j++)
#pragma unroll
            for (int q = 0; q < 4; q++) acc[i][j][q] = 0.f;

    float4 aR[8];

    auto ldg_A = [&](int c) {
        const int k0 = kbase + c * 64;
        const bool docopy = ((c & 1) == bx);
#pragma unroll
        for (int p = 0; p < 8; ++p) {
            int row = p * 16 + arow;
            aR[p] = *(const float4*)(Ab + (size_t)row * SRCL + k0 + ac4 * 4);
            if (docopy)
                *(float4*)(weights + ((size_t)b * TGT + m0 + row) * SRCL + k0 + ac4 * 4) = aR[p];
        }
    };
    auto cp_B = [&](int c, uint32_t bufb) {
        const int k0 = kbase + c * 64;
        const __nv_bfloat16* hsrc = g_vhi + ((size_t)(b * EDIM + n0) * SRCL + k0);
        const __nv_bfloat16* lsrc = g_vlo + ((size_t)(b * EDIM + n0) * SRCL + k0);
#pragma unroll
        for (int q = 0; q < 4; ++q) {
            int idx = tid + 256 * q;
            int row = idx >> 3;          // 0..127 (n)
            int c16 = idx & 7;           // 16B chunk in 128B row
            uint32_t doff = SWZ((uint32_t)(row * 128 + c16 * 16));
            cpasync16(bufb + 32768 + doff, hsrc + (size_t)row * SRCL + c16 * 8);
            cpasync16(bufb + 49152 + doff, lsrc + (size_t)row * SRCL + c16 * 8);
        }
        cpasync_commit();
    };

    // prologue
    ldg_A(0);
    cp_B(0, sb);

#pragma unroll 1
    for (int c = 0; c < NC; ++c) {
        const uint32_t bufb = sb + (uint32_t)(c & 1) * G1_STAGE;
        // STS A(c) (cvt to hi/lo bf16, SW128 rows [m][k] 128B)
#pragma unroll
        for (int p = 0; p < 8; ++p) {
            int row = p * 16 + arow;
            uint32_t off = SWZ((uint32_t)(row * 128 + ac4 * 8));
            uint32_t h0, l0, h1, l1;
            cvt2(aR[p].x, aR[p].y, h0, l0);
            cvt2(aR[p].z, aR[p].w, h1, l1);
            sts64(bufb + off, h0, h1);           // A_hi
            sts64(bufb + 16384 + off, l0, l1);   // A_lo
        }
        cpasync_wait0();     // B(c) arrived
        __syncthreads();

        if (c + 1 < NC) {
            cp_B(c + 1, sb + (uint32_t)((c + 1) & 1) * G1_STAGE);  // overlaps MMA
            ldg_A(c + 1);
        }

        // MMA over staged chunk: 4 k16 steps
        const int r16 = lane & 15;
        const int hA  = lane >> 4;
        const int r8  = lane & 7;
        const int hb  = (lane >> 3) & 1;
#pragma unroll
        for (int kk = 0; kk < 4; ++kk) {
            uint32_t ah[4][4], al[4][4];
#pragma unroll
            for (int mi = 0; mi < 4; ++mi) {
                uint32_t off = SWZ((uint32_t)((wm * 64 + mi * 16 + r16) * 128 + kk * 32 + hA * 16));
                ldsm_x4(ah[mi][0], ah[mi][1], ah[mi][2], ah[mi][3], bufb + off);
                ldsm_x4(al[mi][0], al[mi][1], al[mi][2], al[mi][3], bufb + 16384 + off);
            }
            uint32_t bh[4][2], bl[4][2];
#pragma unroll
            for (int nj = 0; nj < 4; ++nj) {
                uint32_t off = SWZ((uint32_t)((wn * 32 + nj * 8 + r8) * 128 + kk * 32 + hb * 16));
                ldsm_x2(bh[nj][0], bh[nj][1], bufb + 32768 + off);
                ldsm_x2(bl[nj][0], bl[nj][1], bufb + 49152 + off);
            }
#pragma unroll
            for (int mi = 0; mi < 4; ++mi)
#pragma unroll
                for (int nj = 0; nj < 4; ++nj) {
                    mma_bf16(acc[mi][nj][0], acc[mi][nj][1], acc[mi][nj][2], acc[mi][nj][3],
                             ah[mi][0], ah[mi][1], ah[mi][2], ah[mi][3], bh[nj][0], bh[nj][1]);
                    mma_bf16(acc[mi][nj][0], acc[mi][nj][1], acc[mi][nj][2], acc[mi][nj][3],
                             ah[mi][0], ah[mi][1], ah[mi][2], ah[mi][3], bl[nj][0], bl[nj][1]);
                    mma_bf16(acc[mi][nj][0], acc[mi][nj][1], acc[mi][nj][2], acc[mi][nj][3],
                             al[mi][0], al[mi][1], al[mi][2], al[mi][3], bh[nj][0], bh[nj][1]);
                }
        }
        __syncthreads();
    }

    // epilogue: write partial into g_O[ks]
    const int quad = lane >> 2;
    const int qt   = lane & 3;
#pragma unroll
    for (int mi = 0; mi < 4; ++mi)
#pragma unroll
        for (int nj = 0; nj < 4; ++nj) {
            int row = m0 + wm * 64 + mi * 16 + quad;
            int col = n0 + wn * 32 + nj * 8 + qt * 2;
            float* o0 = g_O + (size_t)ks * PARTSZ + ((size_t)b * TGT + row) * EDIM + col;
            *(float2*)o0 = make_float2(acc[mi][nj][0], acc[mi][nj][1]);
            *(float2*)(o0 + 8 * EDIM) = make_float2(acc[mi][nj][2], acc[mi][nj][3]);
        }
}

// ---------------------------------------------------------------------------
// GEMM2: out[64x64] = (sum of 4 partials)[64x256] @ W^T + bias  (R5 shape)
// 256 thr, 8 warps as 2M x 4N (warp 32x16), BK=64, NC=4, grid (4,4,8)
// ---------------------------------------------------------------------------
#define G2_STAGE 32768   // AH 8K | AL 8K | BH 8K | BL 8K
#define G2_SMEM (2 * G2_STAGE)

__global__ void __launch_bounds__(256, 2) gemm2_kernel(
    const float* __restrict__ W, const float* __restrict__ bias,
    float* __restrict__ outp)
{
    extern __shared__ char smem[];
    const uint32_t sb = smem_u32(smem);
    const int tid  = threadIdx.x;
    const int wid  = tid >> 5;
    const int lane = tid & 31;
    const int b    = blockIdx.z;
    const int m0   = blockIdx.y * 64;
    const int n0   = blockIdx.x * 64;
    const int wm   = wid & 1;
    const int wn   = wid >> 1;
    constexpr int NC = EDIM / 64;

    const float* Ag = (const float*)g_O + ((size_t)b * TGT + m0) * EDIM;

    float acc[2][2][4];
#pragma unroll
    for (int i = 0; i < 2; i++)
#pragma unroll
        for (int j = 0; j < 2; j++)
#pragma unroll
            for (int q = 0; q < 4; q++) acc[i][j][q] = 0.f;

    float4 aR[4], bR[4];
    const int rA = tid >> 4;   // 0..15
    const int c4 = tid & 15;

    auto load_chunk = [&](int k0) {
#pragma unroll
        for (int j = 0; j < 4; ++j) {
            int row = j * 16 + rA;
            const float* a0 = Ag + (size_t)row * EDIM + k0 + c4 * 4;
            float4 v  = *(const float4*)a0;
            float4 v1 = *(const float4*)(a0 + PARTSZ);
            float4 v2 = *(const float4*)(a0 + 2 * PARTSZ);
            float4 v3 = *(const float4*)(a0 + 3 * PARTSZ);
            v.x += v1.x + v2.x + v3.x;
            v.y += v1.y + v2.y + v3.y;
            v.z += v1.z + v2.z + v3.z;
            v.w += v1.w + v2.w + v3.w;
            aR[j] = v;
            bR[j] = *(const float4*)(W + (size_t)(n0 + row) * EDIM + k0 + c4 * 4);
        }
    };

    load_chunk(0);

#pragma unroll 1
    for (int c = 0; c < NC; ++c) {
        const uint32_t bufb = sb + (uint32_t)(c & 1) * G2_STAGE;
#pragma unroll
        for (int j = 0; j < 4; ++j) {
            int row = j * 16 + rA;
            uint32_t off = SWZ((uint32_t)(row * 128 + c4 * 8));
            uint32_t h0, l0, h1, l1;
            cvt2(aR[j].x, aR[j].y, h0, l0);
            cvt2(aR[j].z, aR[j].w, h1, l1);
            sts64(bufb + off, h0, h1);
            sts64(bufb + 8192 + off, l0, l1);
            cvt2(bR[j].x, bR[j].y, h0, l0);
            cvt2(bR[j].z, bR[j].w, h1, l1);
            sts64(bufb + 16384 + off, h0, h1);
            sts64(bufb + 24576 + off, l0, l1);
        }
        __syncthreads();

        if (c + 1 < NC) load_chunk((c + 1) * 64);

        const int r16 = lane & 15;
        const int hA  = lane >> 4;
        const int r8  = lane & 7;
        const int hb  = (lane >> 3) & 1;
#pragma unroll
        for (int kk = 0; kk < 4; ++kk) {
            uint32_t ah[2][4], al[2][4];
#pragma unroll
            for (int mi = 0; mi < 2; ++mi) {
                uint32_t off = SWZ((uint32_t)((wm * 32 + mi * 16 + r16) * 128 + kk * 32 + hA * 16));
                ldsm_x4(ah[mi][0], ah[mi][1], ah[mi][2], ah[mi][3], bufb + off);
                ldsm_x4(al[mi][0], al[mi][1], al[mi][2], al[mi][3], bufb + 8192 + off);
            }
            uint32_t bh[2][2], bl[2][2];
#pragma unroll
            for (int j = 0; j < 2; ++j) {
                uint32_t off = SWZ((uint32_t)((wn * 16 + j * 8 + r8) * 128 + kk * 32 + hb * 16));
                ldsm_x2(bh[j][0], bh[j][1], bufb + 16384 + off);
                ldsm_x2(bl[j][0], bl[j][1], bufb + 24576 + off);
            }
#pragma unroll
            for (int mi = 0; mi < 2; ++mi)
#pragma unroll
                for (int j = 0; j < 2; ++j) {
                    mma_bf16(acc[mi][j][0], acc[mi][j][1], acc[mi][j][2], acc[mi][j][3],
                             ah[mi][0], ah[mi][1], ah[mi][2], ah[mi][3], bh[j][0], bh[j][1]);
                    mma_bf16(acc[mi][j][0], acc[mi][j][1], acc[mi][j][2], acc[mi][j][3],
                             ah[mi][0], ah[mi][1], ah[mi][2], ah[mi][3], bl[j][0], bl[j][1]);
                    mma_bf16(acc[mi][j][0], acc[mi][j][1], acc[mi][j][2], acc[mi][j][3],
                             al[mi][0], al[mi][1], al[mi][2], al[mi][3], bh[j][0], bh[j][1]);
                }
        }
    }

    const int quad = lane >> 2;
    const int qt   = lane & 3;
#pragma unroll
    for (int mi = 0; mi < 2; ++mi)
#pragma unroll
        for (int j = 0; j < 2; ++j) {
            int row = m0 + wm * 32 + mi * 16 + quad;
            int col = n0 + wn * 16 + j * 8 + qt * 2;
            float2 bb = *(const float2*)(bias + col);
            *(float2*)(outp + ((size_t)row * BSZ + b) * EDIM + col) =
                make_float2(acc[mi][j][0] + bb.x, acc[mi][j][1] + bb.y);
            *(float2*)(outp + ((size_t)(row + 8) * BSZ + b) * EDIM + col) =
                make_float2(acc[mi][j][2] + bb.x, acc[mi][j][3] + bb.y);
        }
}

extern "C" void kernel_launch(void* const* d_in, const int* in_sizes, int n_in,
                              void* d_out, int out_size) {
    const float* value = (const float*)d_in[2];
    const float* mask  = (const float*)d_in[3];
    const float* W     = (const float*)d_in[4];
    const float* bias  = (const float*)d_in[5];
    float* out = (float*)d_out;

    float* attn_out = out;                               // (TGT, BSZ, E)
    float* weights  = out + (size_t)TGT * BSZ * EDIM;    // (BSZ, TGT, SRC)

    cudaFuncSetAttribute(gemm1_kernel, cudaFuncAttributeMaxDynamicSharedMemorySize, G1_SMEM);
    cudaFuncSetAttribute(gemm2_kernel, cudaFuncAttributeMaxDynamicSharedMemorySize, G2_SMEM);

    // 1) prep: value -> bf16 hi/lo [b][n][k]
    {
        dim3 grid(SRCL / 64, EDIM / 32, BSZ);
        prep_value<<<grid, dim3(32, 8)>>>(value);
    }
    // 2) GEMM1: split-K=4, CTA 128x128; fused weights copy
    {
        dim3 grid(2, 2, BSZ * SPLITK);   // 128 CTAs
        gemm1_kernel<<<grid, 256, G1_SMEM>>>(mask, weights);
    }
    // 3) GEMM2
    {
        dim3 grid(4, 4, BSZ);            // 128 CTAs
        gemm2_kernel<<<grid, 256, G2_SMEM>>>(W, bias, attn_out);
    }
}

// round 9
// speedup vs baseline: 1.5078x; 1.1270x over previous
#include <cuda_runtime.h>
#include <cuda_bf16.h>
#include <cstdint>
#include <cstddef>

#define TGT 256
#define BSZ 8
#define EDIM 256
#define SRCL 4096
#define PARTSZ (BSZ * TGT * EDIM)
#define SPLITK 4

// Split-K partials for GEMM1 (4 x 2MB)
__device__ float g_O[SPLITK * PARTSZ];

#define SWZ(o) ((o) ^ (((o) >> 3) & 0x70u))

static __device__ __forceinline__ uint32_t smem_u32(const void* p) {
    uint32_t a;
    asm("{ .reg .u64 t; cvta.to.shared.u64 t, %1; cvt.u32.u64 %0, t; }" : "=r"(a) : "l"(p));
    return a;
}
// fp32 pair -> bf16x2 hi + bf16x2 lo (x0 in low half)
static __device__ __forceinline__ void cvt2(float x0, float x1, uint32_t& h, uint32_t& l) {
    asm("cvt.rn.bf16x2.f32 %0, %1, %2;" : "=r"(h) : "f"(x1), "f"(x0));
    float h0 = __uint_as_float(h << 16);
    float h1 = __uint_as_float(h & 0xffff0000u);
    float r0 = x0 - h0;
    float r1 = x1 - h1;
    asm("cvt.rn.bf16x2.f32 %0, %1, %2;" : "=r"(l) : "f"(r1), "f"(r0));
}
static __device__ __forceinline__ void sts64(uint32_t addr, uint32_t a, uint32_t b) {
    asm volatile("st.shared.v2.b32 [%0], {%1, %2};" :: "r"(addr), "r"(a), "r"(b) : "memory");
}
static __device__ __forceinline__ void cpasync16(uint32_t dst, const void* src) {
    asm volatile("cp.async.cg.shared.global [%0], [%1], 16;" :: "r"(dst), "l"(src) : "memory");
}
static __device__ __forceinline__ void cpasync_commit() {
    asm volatile("cp.async.commit_group;" ::: "memory");
}
template <int N>
static __device__ __forceinline__ void cpasync_wait() {
    asm volatile("cp.async.wait_group %0;" :: "n"(N) : "memory");
}
static __device__ __forceinline__ void ldsm_x4(uint32_t& r0, uint32_t& r1, uint32_t& r2,
                                               uint32_t& r3, uint32_t addr) {
    asm volatile("ldmatrix.sync.aligned.m8n8.x4.shared.b16 {%0,%1,%2,%3}, [%4];"
                 : "=r"(r0), "=r"(r1), "=r"(r2), "=r"(r3) : "r"(addr));
}
static __device__ __forceinline__ void ldsm_x2(uint32_t& r0, uint32_t& r1, uint32_t addr) {
    asm volatile("ldmatrix.sync.aligned.m8n8.x2.shared.b16 {%0,%1}, [%2];"
                 : "=r"(r0), "=r"(r1) : "r"(addr));
}
static __device__ __forceinline__ void ldsm_x2t(uint32_t& r0, uint32_t& r1, uint32_t addr) {
    asm volatile("ldmatrix.sync.aligned.m8n8.x2.trans.shared.b16 {%0,%1}, [%2];"
                 : "=r"(r0), "=r"(r1) : "r"(addr));
}
static __device__ __forceinline__ void mma_bf16(float& c0, float& c1, float& c2, float& c3,
                                                uint32_t a0, uint32_t a1, uint32_t a2,
                                                uint32_t a3, uint32_t b0, uint32_t b1) {
    asm volatile(
        "mma.sync.aligned.m16n8k16.row.col.f32.bf16.bf16.f32 "
        "{%0,%1,%2,%3}, {%4,%5,%6,%7}, {%8,%9}, {%0,%1,%2,%3};"
        : "+f"(c0), "+f"(c1), "+f"(c2), "+f"(c3)
        : "r"(a0), "r"(a1), "r"(a2), "r"(a3), "r"(b0), "r"(b1));
}

// ---------------------------------------------------------------------------
// GEMM1: partial X_b[128x128] over K/4 = mask_b @ value_b  (+ fused weights copy)
// 256 thr, 8 warps as 2M x 4N (warp 64x32), BK=64, double buffered, 1 sync/chunk.
// A: fp32 LDG (reg prefetch) -> cvt -> STS [m][k] SW128 (non-trans ldsm).
// B: cp.async fp32 [k][n] -> staging smem -> cvt -> STS bf16 [k][n] (trans ldsm).
// grid (2 n, 2 m, 8b * 4ks)
// ---------------------------------------------------------------------------
// per-stage bf16 buffers: AH 16K | AL 16K | BH 16K | BL 16K  (B: two 8K halves n<64 / n>=64)
#define G1_STAGE 65536
#define G1_BSTG  131072          // fp32 B staging: 2 x 32K
#define G1_SMEM  (G1_BSTG + 2 * 32768)   // 196608

__global__ void __launch_bounds__(256, 1) gemm1_kernel(
    const float* __restrict__ mask, const float* __restrict__ value,
    float* __restrict__ weights)
{
    extern __shared__ char smem[];
    const uint32_t sb = smem_u32(smem);
    const int tid  = threadIdx.x;
    const int wid  = tid >> 5;
    const int lane = tid & 31;
    const int bx   = blockIdx.x;            // n-tile (0..1)
    const int m0   = blockIdx.y * 128;
    const int n0   = bx * 128;
    const int b    = blockIdx.z >> 2;
    const int ks   = blockIdx.z & 3;
    const int wm   = wid & 1;               // 2 M warps (64 rows)
    const int wn   = wid >> 1;              // 4 N warps (32 cols)
    const int kbase = ks * (SRCL / SPLITK); // KC = 1024
    constexpr int NC = (SRCL / SPLITK) / 64;  // 16 chunks

    const float* Ab = mask + ((size_t)b * TGT + m0) * SRCL;

    const int arow = tid >> 4;   // 0..15 (+p*16)
    const int ac4  = tid & 15;   // float4 col
    const int brow = tid >> 5;   // 0..7 (B staging: +q*8 -> 64 k rows)   [row = idx>>5]
    const int bc4  = tid & 31;   // 0..31 float4 col (128 n)

    float acc[4][4][4];
#pragma unroll
    for (int i = 0; i < 4; i++)
#pragma unroll
        for (int j = 0; j < 4; j++)
#pragma unroll
            for (int q = 0; q < 4; q++) acc[i][j][q] = 0.f;

    float4 aR[8];

    auto ldg_A = [&](int c) {
        const int k0 = kbase + c * 64;
        const bool docopy = ((c & 1) == bx);
#pragma unroll
        for (int p = 0; p < 8; ++p) {
            int row = p * 16 + arow;
            aR[p] = *(const float4*)(Ab + (size_t)row * SRCL + k0 + ac4 * 4);
            if (docopy)
                *(float4*)(weights + ((size_t)b * TGT + m0 + row) * SRCL + k0 + ac4 * 4) = aR[p];
        }
    };
    // cp.async fp32 B chunk c into staging buffer s. Each thread copies slots
    // (tid + 256q); the SAME mapping is used by cvt_B, so wait_group alone
    // gives the issuing thread visibility of its own data.
    auto cp_B = [&](int c, int s) {
        const int k0 = kbase + c * 64;
        const uint32_t dst = sb + G1_BSTG + (uint32_t)s * 32768;
        const float* src = value + (size_t)k0 * (BSZ * EDIM) + b * EDIM + n0;
#pragma unroll
        for (int q = 0; q < 8; ++q) {
            int row = brow + q * 8;          // k row 0..63
            cpasync16(dst + (uint32_t)(row * 512 + bc4 * 16),
                      src + (size_t)row * (BSZ * EDIM) + bc4 * 4);
        }
        cpasync_commit();
    };
    // convert staged fp32 B -> bf16 hi/lo [k][n] (two 8K halves, SW128 in-half)
    auto cvt_B = [&](uint32_t bufb, int s) {
        const uint32_t stg = sb + G1_BSTG + (uint32_t)s * 32768;
#pragma unroll
        for (int q = 0; q < 8; ++q) {
            int row = brow + q * 8;          // k
            int n   = bc4 * 4;               // 0..124
            float4 v;
            asm volatile("ld.shared.v4.b32 {%0,%1,%2,%3}, [%4];"
                         : "=f"(v.x), "=f"(v.y), "=f"(v.z), "=f"(v.w)
                         : "r"(stg + (uint32_t)(row * 512 + bc4 * 16)));
            uint32_t h0, l0, h1, l1;
            cvt2(v.x, v.y, h0, l0);
            cvt2(v.z, v.w, h1, l1);
            uint32_t half = (n >= 64) ? 8192u : 0u;
            uint32_t off  = half + SWZ((uint32_t)(row * 128 + (n & 63) * 2));
            sts64(bufb + 32768 + off, h0, h1);   // B_hi
            sts64(bufb + 49152 + off, l0, l1);   // B_lo
        }
    };

    // prologue
    cp_B(0, 0);
    ldg_A(0);

#pragma unroll 1
    for (int c = 0; c < NC; ++c) {
        const uint32_t bufb = sb + (uint32_t)(c & 1) * G1_STAGE;
        if (c + 1 < NC) { cp_B(c + 1, (c + 1) & 1); cpasync_wait<1>(); }
        else            { cpasync_wait<0>(); }

        // STS A(c)
#pragma unroll
        for (int p = 0; p < 8; ++p) {
            int row = p * 16 + arow;
            uint32_t off = SWZ((uint32_t)(row * 128 + ac4 * 8));
            uint32_t h0, l0, h1, l1;
            cvt2(aR[p].x, aR[p].y, h0, l0);
            cvt2(aR[p].z, aR[p].w, h1, l1);
            sts64(bufb + off, h0, h1);           // A_hi
            sts64(bufb + 16384 + off, l0, l1);   // A_lo
        }
        // cvt + STS B(c) from staging
        cvt_B(bufb, c & 1);
        __syncthreads();

        if (c + 1 < NC) ldg_A(c + 1);

        // MMA over staged chunk: 4 k16 steps
        const int r16 = lane & 15;
        const int hA  = lane >> 4;
#pragma unroll
        for (int kk = 0; kk < 4; ++kk) {
            uint32_t ah[4][4], al[4][4];
#pragma unroll
            for (int mi = 0; mi < 4; ++mi) {
                uint32_t off = SWZ((uint32_t)((wm * 64 + mi * 16 + r16) * 128 + kk * 32 + hA * 16));
                ldsm_x4(ah[mi][0], ah[mi][1], ah[mi][2], ah[mi][3], bufb + off);
                ldsm_x4(al[mi][0], al[mi][1], al[mi][2], al[mi][3], bufb + 16384 + off);
            }
            uint32_t bh[4][2], bl[4][2];
#pragma unroll
            for (int nj = 0; nj < 4; ++nj) {
                int nn = wn * 32 + nj * 8;
                uint32_t half = (nn >= 64) ? 8192u : 0u;
                uint32_t off = half + SWZ((uint32_t)((kk * 16 + r16) * 128 + (nn & 63) * 2));
                ldsm_x2t(bh[nj][0], bh[nj][1], bufb + 32768 + off);
                ldsm_x2t(bl[nj][0], bl[nj][1], bufb + 49152 + off);
            }
#pragma unroll
            for (int mi = 0; mi < 4; ++mi)
#pragma unroll
                for (int nj = 0; nj < 4; ++nj) {
                    mma_bf16(acc[mi][nj][0], acc[mi][nj][1], acc[mi][nj][2], acc[mi][nj][3],
                             ah[mi][0], ah[mi][1], ah[mi][2], ah[mi][3], bh[nj][0], bh[nj][1]);
                    mma_bf16(acc[mi][nj][0], acc[mi][nj][1], acc[mi][nj][2], acc[mi][nj][3],
                             ah[mi][0], ah[mi][1], ah[mi][2], ah[mi][3], bl[nj][0], bl[nj][1]);
                    mma_bf16(acc[mi][nj][0], acc[mi][nj][1], acc[mi][nj][2], acc[mi][nj][3],
                             al[mi][0], al[mi][1], al[mi][2], al[mi][3], bh[nj][0], bh[nj][1]);
                }
        }
    }

    // epilogue: write partial into g_O[ks]
    const int quad = lane >> 2;
    const int qt   = lane & 3;
#pragma unroll
    for (int mi = 0; mi < 4; ++mi)
#pragma unroll
        for (int nj = 0; nj < 4; ++nj) {
            int row = m0 + wm * 64 + mi * 16 + quad;
            int col = n0 + wn * 32 + nj * 8 + qt * 2;
            float* o0 = g_O + (size_t)ks * PARTSZ + ((size_t)b * TGT + row) * EDIM + col;
            *(float2*)o0 = make_float2(acc[mi][nj][0], acc[mi][nj][1]);
            *(float2*)(o0 + 8 * EDIM) = make_float2(acc[mi][nj][2], acc[mi][nj][3]);
        }
}

// ---------------------------------------------------------------------------
// GEMM2: out[64x64] = (sum of 4 partials)[64x256] @ W^T + bias
// 256 thr, 8 warps as 2M x 4N (warp 32x16), BK=64, NC=4, grid (4,4,8)
// ---------------------------------------------------------------------------
#define G2_STAGE 32768   // AH 8K | AL 8K | BH 8K | BL 8K
#define G2_SMEM (2 * G2_STAGE)

__global__ void __launch_bounds__(256, 2) gemm2_kernel(
    const float* __restrict__ W, const float* __restrict__ bias,
    float* __restrict__ outp)
{
    extern __shared__ char smem[];
    const uint32_t sb = smem_u32(smem);
    const int tid  = threadIdx.x;
    const int wid  = tid >> 5;
    const int lane = tid & 31;
    const int b    = blockIdx.z;
    const int m0   = blockIdx.y * 64;
    const int n0   = blockIdx.x * 64;
    const int wm   = wid & 1;
    const int wn   = wid >> 1;
    constexpr int NC = EDIM / 64;

    const float* Ag = (const float*)g_O + ((size_t)b * TGT + m0) * EDIM;

    float acc[2][2][4];
#pragma unroll
    for (int i = 0; i < 2; i++)
#pragma unroll
        for (int j = 0; j < 2; j++)
#pragma unroll
            for (int q = 0; q < 4; q++) acc[i][j][q] = 0.f;

    float4 aR[4], bR[4];
    const int rA = tid >> 4;   // 0..15
    const int c4 = tid & 15;

    auto load_chunk = [&](int k0) {
#pragma unroll
        for (int j = 0; j < 4; ++j) {
            int row = j * 16 + rA;
            const float* a0 = Ag + (size_t)row * EDIM + k0 + c4 * 4;
            float4 v  = *(const float4*)a0;
            float4 v1 = *(const float4*)(a0 + PARTSZ);
            float4 v2 = *(const float4*)(a0 + 2 * PARTSZ);
            float4 v3 = *(const float4*)(a0 + 3 * PARTSZ);
            v.x += v1.x + v2.x + v3.x;
            v.y += v1.y + v2.y + v3.y;
            v.z += v1.z + v2.z + v3.z;
            v.w += v1.w + v2.w + v3.w;
            aR[j] = v;
            bR[j] = *(const float4*)(W + (size_t)(n0 + row) * EDIM + k0 + c4 * 4);
        }
    };

    load_chunk(0);

#pragma unroll 1
    for (int c = 0; c < NC; ++c) {
        const uint32_t bufb = sb + (uint32_t)(c & 1) * G2_STAGE;
#pragma unroll
        for (int j = 0; j < 4; ++j) {
            int row = j * 16 + rA;
            uint32_t off = SWZ((uint32_t)(row * 128 + c4 * 8));
            uint32_t h0, l0, h1, l1;
            cvt2(aR[j].x, aR[j].y, h0, l0);
            cvt2(aR[j].z, aR[j].w, h1, l1);
            sts64(bufb + off, h0, h1);
            sts64(bufb + 8192 + off, l0, l1);
            cvt2(bR[j].x, bR[j].y, h0, l0);
            cvt2(bR[j].z, bR[j].w, h1, l1);
            sts64(bufb + 16384 + off, h0, h1);
            sts64(bufb + 24576 + off, l0, l1);
        }
        __syncthreads();

        if (c + 1 < NC) load_chunk((c + 1) * 64);

        const int r16 = lane & 15;
        const int hA  = lane >> 4;
        const int r8  = lane & 7;
        const int hb  = (lane >> 3) & 1;
#pragma unroll
        for (int kk = 0; kk < 4; ++kk) {
            uint32_t ah[2][4], al[2][4];
#pragma unroll
            for (int mi = 0; mi < 2; ++mi) {
                uint32_t off = SWZ((uint32_t)((wm * 32 + mi * 16 + r16) * 128 + kk * 32 + hA * 16));
                ldsm_x4(ah[mi][0], ah[mi][1], ah[mi][2], ah[mi][3], bufb + off);
                ldsm_x4(al[mi][0], al[mi][1], al[mi][2], al[mi][3], bufb + 8192 + off);
            }
            uint32_t bh[2][2], bl[2][2];
#pragma unroll
            for (int j = 0; j < 2; ++j) {
                uint32_t off = SWZ((uint32_t)((wn * 16 + j * 8 + r8) * 128 + kk * 32 + hb * 16));
                ldsm_x2(bh[j][0], bh[j][1], bufb + 16384 + off);
                ldsm_x2(bl[j][0], bl[j][1], bufb + 24576 + off);
            }
#pragma unroll
            for (int mi = 0; mi < 2; ++mi)
#pragma unroll
                for (int j = 0; j < 2; ++j) {
                    mma_bf16(acc[mi][j][0], acc[mi][j][1], acc[mi][j][2], acc[mi][j][3],
                             ah[mi][0], ah[mi][1], ah[mi][2], ah[mi][3], bh[j][0], bh[j][1]);
                    mma_bf16(acc[mi][j][0], acc[mi][j][1], acc[mi][j][2], acc[mi][j][3],
                             ah[mi][0], ah[mi][1], ah[mi][2], ah[mi][3], bl[j][0], bl[j][1]);
                    mma_bf16(acc[mi][j][0], acc[mi][j][1], acc[mi][j][2], acc[mi][j][3],
                             al[mi][0], al[mi][1], al[mi][2], al[mi][3], bh[j][0], bh[j][1]);
                }
        }
    }

    const int quad = lane >> 2;
    const int qt   = lane & 3;
#pragma unroll
    for (int mi = 0; mi < 2; ++mi)
#pragma unroll
        for (int j = 0; j < 2; ++j) {
            int row = m0 + wm * 32 + mi * 16 + quad;
            int col = n0 + wn * 16 + j * 8 + qt * 2;
            float2 bb = *(const float2*)(bias + col);
            *(float2*)(outp + ((size_t)row * BSZ + b) * EDIM + col) =
                make_float2(acc[mi][j][0] + bb.x, acc[mi][j][1] + bb.y);
            *(float2*)(outp + ((size_t)(row + 8) * BSZ + b) * EDIM + col) =
                make_float2(acc[mi][j][2] + bb.x, acc[mi][j][3] + bb.y);
        }
}

extern "C" void kernel_launch(void* const* d_in, const int* in_sizes, int n_in,
                              void* d_out, int out_size) {
    const float* value = (const float*)d_in[2];
    const float* mask  = (const float*)d_in[3];
    const float* W     = (const float*)d_in[4];
    const float* bias  = (const float*)d_in[5];
    float* out = (float*)d_out;

    float* attn_out = out;                               // (TGT, BSZ, E)
    float* weights  = out + (size_t)TGT * BSZ * EDIM;    // (BSZ, TGT, SRC)

    cudaFuncSetAttribute(gemm1_kernel, cudaFuncAttributeMaxDynamicSharedMemorySize, G1_SMEM);
    cudaFuncSetAttribute(gemm2_kernel, cudaFuncAttributeMaxDynamicSharedMemorySize, G2_SMEM);

    // GEMM1: split-K=4, CTA 128x128; fused weights copy; in-kernel B convert
    {
        dim3 grid(2, 2, BSZ * SPLITK);   // 128 CTAs
        gemm1_kernel<<<grid, 256, G1_SMEM>>>(mask, value, weights);
    }
    // GEMM2: out = (sum partials) @ W^T + bias
    {
        dim3 grid(4, 4, BSZ);            // 128 CTAs
        gemm2_kernel<<<grid, 256, G2_SMEM>>>(W, bias, attn_out);
    }
}

// round 10
// speedup vs baseline: 1.5604x; 1.0349x over previous
#include <cuda_runtime.h>
#include <cuda_bf16.h>
#include <cstdint>
#include <cstddef>

#define TGT 256
#define BSZ 8
#define EDIM 256
#define SRCL 4096
#define PARTSZ (BSZ * TGT * EDIM)
#define SPLITK 4

// Split-K partials for GEMM1 (4 x 2MB)
__device__ float g_O[SPLITK * PARTSZ];

#define SWZ(o) ((o) ^ (((o) >> 3) & 0x70u))

static __device__ __forceinline__ uint32_t smem_u32(const void* p) {
    uint32_t a;
    asm("{ .reg .u64 t; cvta.to.shared.u64 t, %1; cvt.u32.u64 %0, t; }" : "=r"(a) : "l"(p));
    return a;
}
// fp32 pair -> bf16x2 hi + bf16x2 lo (x0 in low half)
static __device__ __forceinline__ void cvt2(float x0, float x1, uint32_t& h, uint32_t& l) {
    asm("cvt.rn.bf16x2.f32 %0, %1, %2;" : "=r"(h) : "f"(x1), "f"(x0));
    float h0 = __uint_as_float(h << 16);
    float h1 = __uint_as_float(h & 0xffff0000u);
    float r0 = x0 - h0;
    float r1 = x1 - h1;
    asm("cvt.rn.bf16x2.f32 %0, %1, %2;" : "=r"(l) : "f"(r1), "f"(r0));
}
static __device__ __forceinline__ void sts64(uint32_t addr, uint32_t a, uint32_t b) {
    asm volatile("st.shared.v2.b32 [%0], {%1, %2};" :: "r"(addr), "r"(a), "r"(b) : "memory");
}
static __device__ __forceinline__ void ldsm_x4(uint32_t& r0, uint32_t& r1, uint32_t& r2,
                                               uint32_t& r3, uint32_t addr) {
    asm volatile("ldmatrix.sync.aligned.m8n8.x4.shared.b16 {%0,%1,%2,%3}, [%4];"
                 : "=r"(r0), "=r"(r1), "=r"(r2), "=r"(r3) : "r"(addr));
}
static __device__ __forceinline__ void ldsm_x2(uint32_t& r0, uint32_t& r1, uint32_t addr) {
    asm volatile("ldmatrix.sync.aligned.m8n8.x2.shared.b16 {%0,%1}, [%2];"
                 : "=r"(r0), "=r"(r1) : "r"(addr));
}
static __device__ __forceinline__ void ldsm_x2t(uint32_t& r0, uint32_t& r1, uint32_t addr) {
    asm volatile("ldmatrix.sync.aligned.m8n8.x2.trans.shared.b16 {%0,%1}, [%2];"
                 : "=r"(r0), "=r"(r1) : "r"(addr));
}
static __device__ __forceinline__ void mma_bf16(float& c0, float& c1, float& c2, float& c3,
                                                uint32_t a0, uint32_t a1, uint32_t a2,
                                                uint32_t a3, uint32_t b0, uint32_t b1) {
    asm volatile(
        "mma.sync.aligned.m16n8k16.row.col.f32.bf16.bf16.f32 "
        "{%0,%1,%2,%3}, {%4,%5,%6,%7}, {%8,%9}, {%0,%1,%2,%3};"
        : "+f"(c0), "+f"(c1), "+f"(c2), "+f"(c3)
        : "r"(a0), "r"(a1), "r"(a2), "r"(a3), "r"(b0), "r"(b1));
}

// ---------------------------------------------------------------------------
// GEMM1: partial X_b[128x128] over K/4 = mask_b @ value_b  (+ fused weights copy)
// 256 thr, 8 warps as 2M x 4N (warp 64x32), BK=64, double buffered, 1 sync/chunk.
// A: fp32 LDG (reg prefetch) -> cvt -> STS [m][k] SW128 (non-trans ldsm).
// B: fp32 LDG (reg prefetch) -> cvt -> STS bf16 [k][n], two 8K halves (trans ldsm).
// grid (2 n, 2 m, 8b * 4ks)
// ---------------------------------------------------------------------------
// per-stage: AH 16K | AL 16K | BH 16K | BL 16K  (B halves: n<64 at +0, n>=64 at +8K)
#define G1_STAGE 65536
#define G1_SMEM  (2 * G1_STAGE)

__global__ void __launch_bounds__(256, 1) gemm1_kernel(
    const float* __restrict__ mask, const float* __restrict__ value,
    float* __restrict__ weights)
{
    extern __shared__ char smem[];
    const uint32_t sb = smem_u32(smem);
    const int tid  = threadIdx.x;
    const int wid  = tid >> 5;
    const int lane = tid & 31;
    const int bx   = blockIdx.x;            // n-tile (0..1)
    const int m0   = blockIdx.y * 128;
    const int n0   = bx * 128;
    const int b    = blockIdx.z >> 2;
    const int ks   = blockIdx.z & 3;
    const int wm   = wid & 1;               // 2 M warps (64 rows)
    const int wn   = wid >> 1;              // 4 N warps (32 cols)
    const int kbase = ks * (SRCL / SPLITK); // KC = 1024
    constexpr int NC = (SRCL / SPLITK) / 64;  // 16 chunks

    const float* Ab = mask + ((size_t)b * TGT + m0) * SRCL;

    const int arow = tid >> 4;   // 0..15 (+p*16)
    const int ac4  = tid & 15;   // float4 col
    const int brow = tid >> 5;   // 0..7 (+q*8 -> 64 k rows)
    const int bc4  = tid & 31;   // 0..31 float4 col (128 n)

    float acc[4][4][4];
#pragma unroll
    for (int i = 0; i < 4; i++)
#pragma unroll
        for (int j = 0; j < 4; j++)
#pragma unroll
            for (int q = 0; q < 4; q++) acc[i][j][q] = 0.f;

    float4 aR[8], bR[8];

    auto ldg_chunk = [&](int c) {
        const int k0 = kbase + c * 64;
        const bool docopy = ((c & 1) == bx);
#pragma unroll
        for (int p = 0; p < 8; ++p) {
            int row = p * 16 + arow;
            aR[p] = *(const float4*)(Ab + (size_t)row * SRCL + k0 + ac4 * 4);
            if (docopy)
                *(float4*)(weights + ((size_t)b * TGT + m0 + row) * SRCL + k0 + ac4 * 4) = aR[p];
        }
        const float* Bb = value + (size_t)k0 * (BSZ * EDIM) + b * EDIM + n0;
#pragma unroll
        for (int q = 0; q < 8; ++q) {
            int row = brow + q * 8;          // k 0..63
            bR[q] = *(const float4*)(Bb + (size_t)row * (BSZ * EDIM) + bc4 * 4);
        }
    };

    ldg_chunk(0);

#pragma unroll 1
    for (int c = 0; c < NC; ++c) {
        const uint32_t bufb = sb + (uint32_t)(c & 1) * G1_STAGE;
        // STS A(c): [m][k] SW128
#pragma unroll
        for (int p = 0; p < 8; ++p) {
            int row = p * 16 + arow;
            uint32_t off = SWZ((uint32_t)(row * 128 + ac4 * 8));
            uint32_t h0, l0, h1, l1;
            cvt2(aR[p].x, aR[p].y, h0, l0);
            cvt2(aR[p].z, aR[p].w, h1, l1);
            sts64(bufb + off, h0, h1);           // A_hi
            sts64(bufb + 16384 + off, l0, l1);   // A_lo
        }
        // STS B(c): [k][n] bf16, two 8K halves
#pragma unroll
        for (int q = 0; q < 8; ++q) {
            int row = brow + q * 8;
            int n   = bc4 * 4;
            uint32_t h0, l0, h1, l1;
            cvt2(bR[q].x, bR[q].y, h0, l0);
            cvt2(bR[q].z, bR[q].w, h1, l1);
            uint32_t half = (n >= 64) ? 8192u : 0u;
            uint32_t off  = half + SWZ((uint32_t)(row * 128 + (n & 63) * 2));
            sts64(bufb + 32768 + off, h0, h1);   // B_hi
            sts64(bufb + 49152 + off, l0, l1);   // B_lo
        }
        __syncthreads();

        if (c + 1 < NC) ldg_chunk(c + 1);   // overlaps MMA below

        // MMA over staged chunk: 4 k16 steps
        const int r16 = lane & 15;
        const int hA  = lane >> 4;
#pragma unroll
        for (int kk = 0; kk < 4; ++kk) {
            uint32_t ah[4][4], al[4][4];
#pragma unroll
            for (int mi = 0; mi < 4; ++mi) {
                uint32_t off = SWZ((uint32_t)((wm * 64 + mi * 16 + r16) * 128 + kk * 32 + hA * 16));
                ldsm_x4(ah[mi][0], ah[mi][1], ah[mi][2], ah[mi][3], bufb + off);
                ldsm_x4(al[mi][0], al[mi][1], al[mi][2], al[mi][3], bufb + 16384 + off);
            }
            uint32_t bh[4][2], bl[4][2];
#pragma unroll
            for (int nj = 0; nj < 4; ++nj) {
                int nn = wn * 32 + nj * 8;
                uint32_t half = (nn >= 64) ? 8192u : 0u;
                uint32_t off = half + SWZ((uint32_t)((kk * 16 + r16) * 128 + (nn & 63) * 2));
                ldsm_x2t(bh[nj][0], bh[nj][1], bufb + 32768 + off);
                ldsm_x2t(bl[nj][0], bl[nj][1], bufb + 49152 + off);
            }
#pragma unroll
            for (int mi = 0; mi < 4; ++mi)
#pragma unroll
                for (int nj = 0; nj < 4; ++nj) {
                    mma_bf16(acc[mi][nj][0], acc[mi][nj][1], acc[mi][nj][2], acc[mi][nj][3],
                             ah[mi][0], ah[mi][1], ah[mi][2], ah[mi][3], bh[nj][0], bh[nj][1]);
                    mma_bf16(acc[mi][nj][0], acc[mi][nj][1], acc[mi][nj][2], acc[mi][nj][3],
                             ah[mi][0], ah[mi][1], ah[mi][2], ah[mi][3], bl[nj][0], bl[nj][1]);
                    mma_bf16(acc[mi][nj][0], acc[mi][nj][1], acc[mi][nj][2], acc[mi][nj][3],
                             al[mi][0], al[mi][1], al[mi][2], al[mi][3], bh[nj][0], bh[nj][1]);
                }
        }
    }

    // epilogue: write partial into g_O[ks]
    const int quad = lane >> 2;
    const int qt   = lane & 3;
#pragma unroll
    for (int mi = 0; mi < 4; ++mi)
#pragma unroll
        for (int nj = 0; nj < 4; ++nj) {
            int row = m0 + wm * 64 + mi * 16 + quad;
            int col = n0 + wn * 32 + nj * 8 + qt * 2;
            float* o0 = g_O + (size_t)ks * PARTSZ + ((size_t)b * TGT + row) * EDIM + col;
            *(float2*)o0 = make_float2(acc[mi][nj][0], acc[mi][nj][1]);
            *(float2*)(o0 + 8 * EDIM) = make_float2(acc[mi][nj][2], acc[mi][nj][3]);
        }
}

// ---------------------------------------------------------------------------
// GEMM2: out[32x64] = (sum of 4 partials)[32x256] @ W^T + bias
// 256 thr, 8 warps as 2M x 4N (warp 16x16), BK=64, NC=4.
// grid (4 n, 8 m, 8 b) = 256 CTAs -> 2 CTAs/SM.
// ---------------------------------------------------------------------------
// per-stage: AH 4K | AL 4K | BH 8K | BL 8K = 24K
#define G2_STAGE 24576
#define G2_SMEM (2 * G2_STAGE)

__global__ void __launch_bounds__(256, 2) gemm2_kernel(
    const float* __restrict__ W, const float* __restrict__ bias,
    float* __restrict__ outp)
{
    extern __shared__ char smem[];
    const uint32_t sb = smem_u32(smem);
    const int tid  = threadIdx.x;
    const int wid  = tid >> 5;
    const int lane = tid & 31;
    const int b    = blockIdx.z;
    const int m0   = blockIdx.y * 32;
    const int n0   = blockIdx.x * 64;
    const int wm   = wid & 1;       // 2 warps in M (16 rows)
    const int wn   = wid >> 1;      // 4 warps in N (16 cols)
    constexpr int NC = EDIM / 64;

    const float* Ag = (const float*)g_O + ((size_t)b * TGT + m0) * EDIM;

    float acc[2][4];
#pragma unroll
    for (int j = 0; j < 2; j++)
#pragma unroll
        for (int q = 0; q < 4; q++) acc[j][q] = 0.f;

    float4 aR[2], bR[4];
    const int rA = tid >> 4;   // 0..15
    const int c4 = tid & 15;

    auto load_chunk = [&](int k0) {
#pragma unroll
        for (int p = 0; p < 2; ++p) {
            int row = p * 16 + rA;
            const float* a0 = Ag + (size_t)row * EDIM + k0 + c4 * 4;
            float4 v  = *(const float4*)a0;
            float4 v1 = *(const float4*)(a0 + PARTSZ);
            float4 v2 = *(const float4*)(a0 + 2 * PARTSZ);
            float4 v3 = *(const float4*)(a0 + 3 * PARTSZ);
            v.x += v1.x + v2.x + v3.x;
            v.y += v1.y + v2.y + v3.y;
            v.z += v1.z + v2.z + v3.z;
            v.w += v1.w + v2.w + v3.w;
            aR[p] = v;
        }
#pragma unroll
        for (int p = 0; p < 4; ++p) {
            int row = p * 16 + rA;
            bR[p] = *(const float4*)(W + (size_t)(n0 + row) * EDIM + k0 + c4 * 4);
        }
    };

    load_chunk(0);

#pragma unroll 1
    for (int c = 0; c < NC; ++c) {
        const uint32_t bufb = sb + (uint32_t)(c & 1) * G2_STAGE;
        uint32_t off = SWZ((uint32_t)(rA * 128 + c4 * 8));
#pragma unroll
        for (int p = 0; p < 2; ++p) {
            uint32_t o = SWZ((uint32_t)((p * 16 + rA) * 128 + c4 * 8));
            uint32_t h0, l0, h1, l1;
            cvt2(aR[p].x, aR[p].y, h0, l0);
            cvt2(aR[p].z, aR[p].w, h1, l1);
            sts64(bufb + o, h0, h1);            // A_hi (4K)
            sts64(bufb + 4096 + o, l0, l1);     // A_lo
        }
        (void)off;
#pragma unroll
        for (int p = 0; p < 4; ++p) {
            uint32_t o = SWZ((uint32_t)((p * 16 + rA) * 128 + c4 * 8));
            uint32_t h0, l0, h1, l1;
            cvt2(bR[p].x, bR[p].y, h0, l0);
            cvt2(bR[p].z, bR[p].w, h1, l1);
            sts64(bufb + 8192 + o, h0, h1);     // B_hi (8K)
            sts64(bufb + 16384 + o, l0, l1);    // B_lo
        }
        __syncthreads();

        if (c + 1 < NC) load_chunk((c + 1) * 64);

        const int r16 = lane & 15;
        const int hA  = lane >> 4;
        const int r8  = lane & 7;
        const int hb  = (lane >> 3) & 1;
#pragma unroll
        for (int kk = 0; kk < 4; ++kk) {
            uint32_t ah[4], al[4];
            {
                uint32_t o = SWZ((uint32_t)((wm * 16 + r16) * 128 + kk * 32 + hA * 16));
                ldsm_x4(ah[0], ah[1], ah[2], ah[3], bufb + o);
                ldsm_x4(al[0], al[1], al[2], al[3], bufb + 4096 + o);
            }
            uint32_t bh[2][2], bl[2][2];
#pragma unroll
            for (int j = 0; j < 2; ++j) {
                uint32_t o = SWZ((uint32_t)((wn * 16 + j * 8 + r8) * 128 + kk * 32 + hb * 16));
                ldsm_x2(bh[j][0], bh[j][1], bufb + 8192 + o);
                ldsm_x2(bl[j][0], bl[j][1], bufb + 16384 + o);
            }
#pragma unroll
            for (int j = 0; j < 2; ++j) {
                mma_bf16(acc[j][0], acc[j][1], acc[j][2], acc[j][3],
                         ah[0], ah[1], ah[2], ah[3], bh[j][0], bh[j][1]);
                mma_bf16(acc[j][0], acc[j][1], acc[j][2], acc[j][3],
                         ah[0], ah[1], ah[2], ah[3], bl[j][0], bl[j][1]);
                mma_bf16(acc[j][0], acc[j][1], acc[j][2], acc[j][3],
                         al[0], al[1], al[2], al[3], bh[j][0], bh[j][1]);
            }
        }
    }

    const int quad = lane >> 2;
    const int qt   = lane & 3;
#pragma unroll
    for (int j = 0; j < 2; ++j) {
        int row = m0 + wm * 16 + quad;
        int col = n0 + wn * 16 + j * 8 + qt * 2;
        float2 bb = *(const float2*)(bias + col);
        *(float2*)(outp + ((size_t)row * BSZ + b) * EDIM + col) =
            make_float2(acc[j][0] + bb.x, acc[j][1] + bb.y);
        *(float2*)(outp + ((size_t)(row + 8) * BSZ + b) * EDIM + col) =
            make_float2(acc[j][2] + bb.x, acc[j][3] + bb.y);
    }
}

extern "C" void kernel_launch(void* const* d_in, const int* in_sizes, int n_in,
                              void* d_out, int out_size) {
    const float* value = (const float*)d_in[2];
    const float* mask  = (const float*)d_in[3];
    const float* W     = (const float*)d_in[4];
    const float* bias  = (const float*)d_in[5];
    float* out = (float*)d_out;

    float* attn_out = out;                               // (TGT, BSZ, E)
    float* weights  = out + (size_t)TGT * BSZ * EDIM;    // (BSZ, TGT, SRC)

    cudaFuncSetAttribute(gemm1_kernel, cudaFuncAttributeMaxDynamicSharedMemorySize, G1_SMEM);
    cudaFuncSetAttribute(gemm2_kernel, cudaFuncAttributeMaxDynamicSharedMemorySize, G2_SMEM);

    // GEMM1: split-K=4, CTA 128x128; fused weights copy
    {
        dim3 grid(2, 2, BSZ * SPLITK);   // 128 CTAs
        gemm1_kernel<<<grid, 256, G1_SMEM>>>(mask, value, weights);
    }
    // GEMM2: out = (sum partials) @ W^T + bias
    {
        dim3 grid(4, 8, BSZ);            // 256 CTAs, 2/SM
        gemm2_kernel<<<grid, 256, G2_SMEM>>>(W, bias, attn_out);
    }
}